// round 7
// baseline (speedup 1.0000x reference)
#include <cuda_runtime.h>
#include <cstdint>

#define N_NODES 100000
#define N_EDGES 1200000
#define C_IN 64
#define C_HID 64
#define C_OUT 32

#define SCAN_B 256
#define NB ((N_NODES + SCAN_B - 1) / SCAN_B)   // 391

// ---------------- scratch (device globals; no allocs allowed) ----------------
__device__ int   g_rowptr[N_NODES + 1];
__device__ int   g_cursor[N_NODES];
__device__ int   g_csrc[N_EDGES];
__device__ int   g_bsum[NB];
__device__ float g_y[N_NODES * C_HID];   // x @ W1_l
__device__ float g_z[N_NODES * C_HID];   // x @ W1_r + b1
__device__ float g_h[N_NODES * C_HID];   // relu(mean(y)+z)
__device__ float g_p[N_NODES * C_OUT];   // h @ W2_l
__device__ float g_q[N_NODES * C_OUT];   // h @ W2_r + b2

// ---------------- CSR build ----------------
__global__ void k_zero_cnt() {
    int i = blockIdx.x * blockDim.x + threadIdx.x;
    if (i < N_NODES) g_cursor[i] = 0;
}

__global__ void k_count(const int* __restrict__ ei) {
    int e = blockIdx.x * blockDim.x + threadIdx.x;
    if (e < N_EDGES) {
        int d = ei[N_EDGES + e];                    // int32 node ids
        if ((unsigned)d < (unsigned)N_NODES)
            atomicAdd(&g_cursor[d], 1);
    }
}

// per-block exclusive scan; block totals to g_bsum.
// Padded Kogge-Stone: low half of s[] stays zero so s[idx-off] is always in-bounds.
__global__ void k_scan_a() {
    __shared__ int s[2 * SCAN_B];
    int t = threadIdx.x;
    int i = blockIdx.x * SCAN_B + t;
    int v = (i < N_NODES) ? g_cursor[i] : 0;
    s[t] = 0;                    // padding (identity for +)
    int idx = SCAN_B + t;
    s[idx] = v;
    __syncthreads();
    #pragma unroll
    for (int off = 1; off < SCAN_B; off <<= 1) {
        int x = s[idx - off];
        __syncthreads();
        s[idx] += x;
        __syncthreads();
    }
    if (i < N_NODES) g_rowptr[i] = s[idx] - v;     // exclusive within block
    if (t == SCAN_B - 1) g_bsum[blockIdx.x] = s[idx];
}

// single-block exclusive scan of block sums (NB=391 <= 512), same padding trick
__global__ void k_scan_b() {
    __shared__ int s[1024];
    int t = threadIdx.x;
    int v = (t < NB) ? g_bsum[t] : 0;
    s[t] = 0;                    // padding
    int idx = 512 + t;
    s[idx] = v;
    __syncthreads();
    #pragma unroll
    for (int off = 1; off < 512; off <<= 1) {
        int x = s[idx - off];
        __syncthreads();
        s[idx] += x;
        __syncthreads();
    }
    if (t < NB) g_bsum[t] = s[idx] - v;            // exclusive
}

__global__ void k_scan_c() {
    int i = blockIdx.x * blockDim.x + threadIdx.x;
    if (i < N_NODES) {
        int r = g_rowptr[i] + g_bsum[i >> 8];
        g_rowptr[i] = r;
        g_cursor[i] = r;
    }
    if (i == 0) g_rowptr[N_NODES] = N_EDGES;
}

__global__ void k_fill(const int* __restrict__ ei) {
    int e = blockIdx.x * blockDim.x + threadIdx.x;
    if (e < N_EDGES) {
        int s = ei[e];
        int d = ei[N_EDGES + e];
        if ((unsigned)s < (unsigned)N_NODES && (unsigned)d < (unsigned)N_NODES) {
            int pos = atomicAdd(&g_cursor[d], 1);
            if ((unsigned)pos < (unsigned)N_EDGES) g_csrc[pos] = s;
        }
    }
}

// ---------------- layer-1 transform: y = x@W1_l, z = x@W1_r + b1 ----------------
__global__ void k_transform1(const float* __restrict__ x,
                             const float* __restrict__ Wl,
                             const float* __restrict__ Wr,
                             const float* __restrict__ b1) {
    __shared__ float sWl[64 * 64];   // transposed: sWl[j*64+k] = Wl[k*64+j]
    __shared__ float sWr[64 * 64];
    __shared__ float sB[64];
    int t = threadIdx.x;
    for (int idx = t; idx < 4096; idx += blockDim.x) {
        int k = idx >> 6, j = idx & 63;
        sWl[j * 64 + k] = Wl[idx];
        sWr[j * 64 + k] = Wr[idx];
    }
    if (t < 64) sB[t] = b1[t];
    __syncthreads();

    int n = blockIdx.x * blockDim.x + t;
    if (n >= N_NODES) return;

    float4 xv[16];
    const float4* xr = (const float4*)(x + (size_t)n * 64);
    #pragma unroll
    for (int i = 0; i < 16; i++) xv[i] = xr[i];

    float* yo = g_y + (size_t)n * 64;
    float* zo = g_z + (size_t)n * 64;
    #pragma unroll 4
    for (int j = 0; j < 64; j++) {
        const float4* wl = (const float4*)(sWl + j * 64);
        const float4* wr = (const float4*)(sWr + j * 64);
        float aL = 0.f, aR = 0.f;
        #pragma unroll
        for (int k = 0; k < 16; k++) {
            float4 a = wl[k], b = wr[k], v = xv[k];
            aL = fmaf(v.x, a.x, aL); aL = fmaf(v.y, a.y, aL);
            aL = fmaf(v.z, a.z, aL); aL = fmaf(v.w, a.w, aL);
            aR = fmaf(v.x, b.x, aR); aR = fmaf(v.y, b.y, aR);
            aR = fmaf(v.z, b.z, aR); aR = fmaf(v.w, b.w, aR);
        }
        yo[j] = aL;
        zo[j] = aR + sB[j];
    }
}

// ---------------- layer-1 aggregate + relu: warp per node ----------------
__global__ void k_agg1() {
    int n = blockIdx.x * 8 + (threadIdx.x >> 5);
    if (n >= N_NODES) return;
    int lane = threadIdx.x & 31;
    int b = g_rowptr[n], eend = g_rowptr[n + 1];
    int deg = eend - b;
    const float2* y2 = (const float2*)g_y;
    float ax = 0.f, ay = 0.f;
    int e = b;
    for (; e + 4 <= eend; e += 4) {
        int s0 = g_csrc[e], s1 = g_csrc[e + 1], s2 = g_csrc[e + 2], s3 = g_csrc[e + 3];
        float2 v0 = y2[(size_t)s0 * 32 + lane];
        float2 v1 = y2[(size_t)s1 * 32 + lane];
        float2 v2 = y2[(size_t)s2 * 32 + lane];
        float2 v3 = y2[(size_t)s3 * 32 + lane];
        ax += (v0.x + v1.x) + (v2.x + v3.x);
        ay += (v0.y + v1.y) + (v2.y + v3.y);
    }
    for (; e < eend; e++) {
        int s = g_csrc[e];
        float2 v = y2[(size_t)s * 32 + lane];
        ax += v.x; ay += v.y;
    }
    float inv = 1.f / (float)(deg > 0 ? deg : 1);
    size_t o = (size_t)n * 64 + lane * 2;
    g_h[o]     = fmaxf(fmaf(ax, inv, g_z[o]), 0.f);
    g_h[o + 1] = fmaxf(fmaf(ay, inv, g_z[o + 1]), 0.f);
}

// ---------------- layer-2 transform: p = h@W2_l, q = h@W2_r + b2 ----------------
__global__ void k_transform2(const float* __restrict__ Wl,
                             const float* __restrict__ Wr,
                             const float* __restrict__ b2) {
    __shared__ float sWl[32 * 64];   // sWl[j*64+k] = Wl[k*32+j]
    __shared__ float sWr[32 * 64];
    __shared__ float sB[32];
    int t = threadIdx.x;
    for (int idx = t; idx < 2048; idx += blockDim.x) {
        int k = idx >> 5, j = idx & 31;
        sWl[j * 64 + k] = Wl[idx];
        sWr[j * 64 + k] = Wr[idx];
    }
    if (t < 32) sB[t] = b2[t];
    __syncthreads();

    int n = blockIdx.x * blockDim.x + t;
    if (n >= N_NODES) return;

    float4 hv[16];
    const float4* hr = (const float4*)(g_h + (size_t)n * 64);
    #pragma unroll
    for (int i = 0; i < 16; i++) hv[i] = hr[i];

    float* po = g_p + (size_t)n * 32;
    float* qo = g_q + (size_t)n * 32;
    #pragma unroll 4
    for (int j = 0; j < 32; j++) {
        const float4* wl = (const float4*)(sWl + j * 64);
        const float4* wr = (const float4*)(sWr + j * 64);
        float aL = 0.f, aR = 0.f;
        #pragma unroll
        for (int k = 0; k < 16; k++) {
            float4 a = wl[k], b = wr[k], v = hv[k];
            aL = fmaf(v.x, a.x, aL); aL = fmaf(v.y, a.y, aL);
            aL = fmaf(v.z, a.z, aL); aL = fmaf(v.w, a.w, aL);
            aR = fmaf(v.x, b.x, aR); aR = fmaf(v.y, b.y, aR);
            aR = fmaf(v.z, b.z, aR); aR = fmaf(v.w, b.w, aR);
        }
        po[j] = aL;
        qo[j] = aR + sB[j];
    }
}

// ---------------- layer-2 aggregate -> output ----------------
__global__ void k_agg2(float* __restrict__ out) {
    int n = blockIdx.x * 8 + (threadIdx.x >> 5);
    if (n >= N_NODES) return;
    int lane = threadIdx.x & 31;
    int b = g_rowptr[n], eend = g_rowptr[n + 1];
    int deg = eend - b;
    float acc = 0.f;
    int e = b;
    for (; e + 4 <= eend; e += 4) {
        int s0 = g_csrc[e], s1 = g_csrc[e + 1], s2 = g_csrc[e + 2], s3 = g_csrc[e + 3];
        float v0 = g_p[(size_t)s0 * 32 + lane];
        float v1 = g_p[(size_t)s1 * 32 + lane];
        float v2 = g_p[(size_t)s2 * 32 + lane];
        float v3 = g_p[(size_t)s3 * 32 + lane];
        acc += (v0 + v1) + (v2 + v3);
    }
    for (; e < eend; e++) {
        acc += g_p[(size_t)g_csrc[e] * 32 + lane];
    }
    float inv = 1.f / (float)(deg > 0 ? deg : 1);
    size_t o = (size_t)n * 32 + lane;
    out[o] = fmaf(acc, inv, g_q[o]);
}

// ---------------- launch ----------------
extern "C" void kernel_launch(void* const* d_in, const int* in_sizes, int n_in,
                              void* d_out, int out_size) {
    // Bind inputs BY ELEMENT COUNT (robust to metadata ordering). All role
    // counts are distinct; for the equal-size weight pairs, *_l precedes *_r
    // in both insertion and alphabetical orderings.
    const float* x   = nullptr;   // 6,400,000
    const int*   ei  = nullptr;   // 2,400,000 (int32 — JAX default x64 off)
    const float* W1l = nullptr;   // 4096 (first)
    const float* W1r = nullptr;   // 4096 (second)
    const float* b1  = nullptr;   // 64
    const float* W2l = nullptr;   // 2048 (first)
    const float* W2r = nullptr;   // 2048 (second)
    const float* b2  = nullptr;   // 32
    for (int i = 0; i < n_in; i++) {
        int sz = in_sizes[i];
        const void* p = d_in[i];
        if      (sz == N_NODES * C_IN)   x  = (const float*)p;
        else if (sz == 2 * N_EDGES)      ei = (const int*)p;
        else if (sz == C_IN * C_HID)   { if (!W1l) W1l = (const float*)p; else W1r = (const float*)p; }
        else if (sz == C_HID)            b1 = (const float*)p;
        else if (sz == C_HID * C_OUT)  { if (!W2l) W2l = (const float*)p; else W2r = (const float*)p; }
        else if (sz == C_OUT)            b2 = (const float*)p;
    }
    float* out = (float*)d_out;
    if (!x || !ei || !W1l || !W1r || !b1 || !W2l || !W2r || !b2) return;

    const int TB = 256;
    int gridN = (N_NODES + TB - 1) / TB;       // 391
    int gridE = (N_EDGES + TB - 1) / TB;       // 4688
    int gridW = (N_NODES + 7) / 8;             // 12500 (warp-per-node, 8 warps/blk)

    // CSR build
    k_zero_cnt<<<gridN, TB>>>();
    k_count<<<gridE, TB>>>(ei);
    k_scan_a<<<NB, SCAN_B>>>();
    k_scan_b<<<1, 512>>>();
    k_scan_c<<<gridN, TB>>>();
    k_fill<<<gridE, TB>>>(ei);

    // layer 1
    k_transform1<<<gridN, TB>>>(x, W1l, W1r, b1);
    k_agg1<<<gridW, TB>>>();

    // layer 2
    k_transform2<<<gridN, TB>>>(W2l, W2r, b2);
    k_agg2<<<gridW, TB>>>(out);
}

// round 8
// speedup vs baseline: 1.0422x; 1.0422x over previous
#include <cuda_runtime.h>
#include <cstdint>

#define N_NODES 100000
#define N_EDGES 1200000
#define C_IN 64
#define C_HID 64
#define C_OUT 32

#define SCAN_B 256
#define NB ((N_NODES + SCAN_B - 1) / SCAN_B)   // 391

#define TB 256
#define GRID_N ((N_NODES + TB - 1) / TB)       // 391
#define GRID_E ((N_EDGES + TB - 1) / TB)       // 4688

// ---------------- scratch (device globals; no allocs allowed) ----------------
__device__ int   g_rowptr[N_NODES + 1];
__device__ int   g_cursor[N_NODES];
__device__ int   g_csrc[N_EDGES];
__device__ int   g_bsum[NB];
__device__ float g_y[N_NODES * C_HID];   // x @ W1_l
__device__ float g_z[N_NODES * C_HID];   // x @ W1_r + b1
__device__ float g_h[N_NODES * C_HID];   // relu(mean(y)+z)
__device__ float g_p[N_NODES * C_OUT];   // h @ W2_l
__device__ float g_q[N_NODES * C_OUT];   // h @ W2_r + b2

// ---------------- packed f32x2 FMA (ptxas never emits FFMA2 from C++) -------
__device__ __forceinline__ unsigned long long ffma2(unsigned long long a,
                                                    unsigned long long b,
                                                    unsigned long long c) {
    unsigned long long d;
    asm("fma.rn.f32x2 %0, %1, %2, %3;" : "=l"(d) : "l"(a), "l"(b), "l"(c));
    return d;
}
__device__ __forceinline__ float f2_sum(unsigned long long v) {
    float lo, hi;
    asm("mov.b64 {%0, %1}, %2;" : "=f"(lo), "=f"(hi) : "l"(v));
    return lo + hi;
}

// ---------------- CSR build ----------------
__global__ void k_zero_cnt() {
    int i = blockIdx.x * blockDim.x + threadIdx.x;
    if (i < N_NODES) g_cursor[i] = 0;
}

__global__ void k_count(const int* __restrict__ ei) {
    int e = blockIdx.x * blockDim.x + threadIdx.x;
    if (e < N_EDGES) {
        int d = ei[N_EDGES + e];                    // int32 node ids
        if ((unsigned)d < (unsigned)N_NODES)
            atomicAdd(&g_cursor[d], 1);
    }
}

// Padded Kogge-Stone scans (low half zero -> s[idx-off] always in-bounds)
__global__ void k_scan_a() {
    __shared__ int s[2 * SCAN_B];
    int t = threadIdx.x;
    int i = blockIdx.x * SCAN_B + t;
    int v = (i < N_NODES) ? g_cursor[i] : 0;
    s[t] = 0;
    int idx = SCAN_B + t;
    s[idx] = v;
    __syncthreads();
    #pragma unroll
    for (int off = 1; off < SCAN_B; off <<= 1) {
        int x = s[idx - off];
        __syncthreads();
        s[idx] += x;
        __syncthreads();
    }
    if (i < N_NODES) g_rowptr[i] = s[idx] - v;
    if (t == SCAN_B - 1) g_bsum[blockIdx.x] = s[idx];
}

__global__ void k_scan_b() {
    __shared__ int s[1024];
    int t = threadIdx.x;
    int v = (t < NB) ? g_bsum[t] : 0;
    s[t] = 0;
    int idx = 512 + t;
    s[idx] = v;
    __syncthreads();
    #pragma unroll
    for (int off = 1; off < 512; off <<= 1) {
        int x = s[idx - off];
        __syncthreads();
        s[idx] += x;
        __syncthreads();
    }
    if (t < NB) g_bsum[t] = s[idx] - v;
}

__global__ void k_scan_c() {
    int i = blockIdx.x * blockDim.x + threadIdx.x;
    if (i < N_NODES) {
        int r = g_rowptr[i] + g_bsum[i >> 8];
        g_rowptr[i] = r;
        g_cursor[i] = r;
    }
    if (i == 0) g_rowptr[N_NODES] = N_EDGES;
}

// ---------------- fused: transform1 (blocks [0,GRID_N)) + fill (rest) -------
// transform1 is independent of the CSR chain; fusing it into the fill launch
// overlaps the fma-bound GEMM with the atomic/memory-bound scatter.
__global__ void __launch_bounds__(TB) k_fill_t1(const int* __restrict__ ei,
                                                const float* __restrict__ x,
                                                const float* __restrict__ Wl,
                                                const float* __restrict__ Wr,
                                                const float* __restrict__ b1) {
    __shared__ float sWl[64 * 64];   // transposed: sWl[j*64+k] = Wl[k*64+j]
    __shared__ float sWr[64 * 64];
    __shared__ float sB[64];

    int t = threadIdx.x;

    if (blockIdx.x >= GRID_N) {
        // ---- fill branch ----
        int e = (blockIdx.x - GRID_N) * TB + t;
        if (e < N_EDGES) {
            int s = ei[e];
            int d = ei[N_EDGES + e];
            if ((unsigned)s < (unsigned)N_NODES && (unsigned)d < (unsigned)N_NODES) {
                int pos = atomicAdd(&g_cursor[d], 1);
                if ((unsigned)pos < (unsigned)N_EDGES) g_csrc[pos] = s;
            }
        }
        return;
    }

    // ---- transform1 branch ----
    for (int idx = t; idx < 4096; idx += TB) {
        int k = idx >> 6, j = idx & 63;
        sWl[j * 64 + k] = Wl[idx];
        sWr[j * 64 + k] = Wr[idx];
    }
    if (t < 64) sB[t] = b1[t];
    __syncthreads();

    int n = blockIdx.x * TB + t;
    if (n >= N_NODES) return;

    // x row as 32 packed f32x2 (register pairs)
    unsigned long long xv[32];
    const ulonglong2* xr = (const ulonglong2*)(x + (size_t)n * 64);
    #pragma unroll
    for (int i = 0; i < 16; i++) { ulonglong2 v = xr[i]; xv[2 * i] = v.x; xv[2 * i + 1] = v.y; }

    float* yo = g_y + (size_t)n * 64;
    float* zo = g_z + (size_t)n * 64;
    #pragma unroll 2
    for (int j = 0; j < 64; j++) {
        const ulonglong2* wl = (const ulonglong2*)(sWl + j * 64);
        const ulonglong2* wr = (const ulonglong2*)(sWr + j * 64);
        unsigned long long aL = 0ull, aR = 0ull;
        #pragma unroll
        for (int m = 0; m < 16; m++) {
            ulonglong2 a = wl[m];
            ulonglong2 b = wr[m];
            aL = ffma2(a.x, xv[2 * m], aL);
            aR = ffma2(b.x, xv[2 * m], aR);
            aL = ffma2(a.y, xv[2 * m + 1], aL);
            aR = ffma2(b.y, xv[2 * m + 1], aR);
        }
        yo[j] = f2_sum(aL);
        zo[j] = f2_sum(aR) + sB[j];
    }
}

// ---------------- layer-1 aggregate + relu: warp per node ----------------
__global__ void k_agg1() {
    int n = blockIdx.x * 8 + (threadIdx.x >> 5);
    if (n >= N_NODES) return;
    int lane = threadIdx.x & 31;
    int b = g_rowptr[n], eend = g_rowptr[n + 1];
    int deg = eend - b;
    const float2* y2 = (const float2*)g_y;
    float ax = 0.f, ay = 0.f;
    int e = b;
    for (; e + 4 <= eend; e += 4) {
        int s0 = g_csrc[e], s1 = g_csrc[e + 1], s2 = g_csrc[e + 2], s3 = g_csrc[e + 3];
        float2 v0 = y2[(size_t)s0 * 32 + lane];
        float2 v1 = y2[(size_t)s1 * 32 + lane];
        float2 v2 = y2[(size_t)s2 * 32 + lane];
        float2 v3 = y2[(size_t)s3 * 32 + lane];
        ax += (v0.x + v1.x) + (v2.x + v3.x);
        ay += (v0.y + v1.y) + (v2.y + v3.y);
    }
    for (; e < eend; e++) {
        int s = g_csrc[e];
        float2 v = y2[(size_t)s * 32 + lane];
        ax += v.x; ay += v.y;
    }
    float inv = 1.f / (float)(deg > 0 ? deg : 1);
    size_t o = (size_t)n * 64 + lane * 2;
    g_h[o]     = fmaxf(fmaf(ax, inv, g_z[o]), 0.f);
    g_h[o + 1] = fmaxf(fmaf(ay, inv, g_z[o + 1]), 0.f);
}

// ---------------- layer-2 transform: p = h@W2_l, q = h@W2_r + b2 ----------------
__global__ void __launch_bounds__(TB) k_transform2(const float* __restrict__ Wl,
                                                   const float* __restrict__ Wr,
                                                   const float* __restrict__ b2) {
    __shared__ float sWl[32 * 64];   // sWl[j*64+k] = Wl[k*32+j]
    __shared__ float sWr[32 * 64];
    __shared__ float sB[32];
    int t = threadIdx.x;
    for (int idx = t; idx < 2048; idx += TB) {
        int k = idx >> 5, j = idx & 31;
        sWl[j * 64 + k] = Wl[idx];
        sWr[j * 64 + k] = Wr[idx];
    }
    if (t < 32) sB[t] = b2[t];
    __syncthreads();

    int n = blockIdx.x * TB + t;
    if (n >= N_NODES) return;

    unsigned long long hv[32];
    const ulonglong2* hr = (const ulonglong2*)(g_h + (size_t)n * 64);
    #pragma unroll
    for (int i = 0; i < 16; i++) { ulonglong2 v = hr[i]; hv[2 * i] = v.x; hv[2 * i + 1] = v.y; }

    float* po = g_p + (size_t)n * 32;
    float* qo = g_q + (size_t)n * 32;
    #pragma unroll 2
    for (int j = 0; j < 32; j++) {
        const ulonglong2* wl = (const ulonglong2*)(sWl + j * 64);
        const ulonglong2* wr = (const ulonglong2*)(sWr + j * 64);
        unsigned long long aL = 0ull, aR = 0ull;
        #pragma unroll
        for (int m = 0; m < 16; m++) {
            ulonglong2 a = wl[m];
            ulonglong2 b = wr[m];
            aL = ffma2(a.x, hv[2 * m], aL);
            aR = ffma2(b.x, hv[2 * m], aR);
            aL = ffma2(a.y, hv[2 * m + 1], aL);
            aR = ffma2(b.y, hv[2 * m + 1], aR);
        }
        po[j] = f2_sum(aL);
        qo[j] = f2_sum(aR) + sB[j];
    }
}

// ---------------- layer-2 aggregate -> output ----------------
__global__ void k_agg2(float* __restrict__ out) {
    int n = blockIdx.x * 8 + (threadIdx.x >> 5);
    if (n >= N_NODES) return;
    int lane = threadIdx.x & 31;
    int b = g_rowptr[n], eend = g_rowptr[n + 1];
    int deg = eend - b;
    float acc = 0.f;
    int e = b;
    for (; e + 4 <= eend; e += 4) {
        int s0 = g_csrc[e], s1 = g_csrc[e + 1], s2 = g_csrc[e + 2], s3 = g_csrc[e + 3];
        float v0 = g_p[(size_t)s0 * 32 + lane];
        float v1 = g_p[(size_t)s1 * 32 + lane];
        float v2 = g_p[(size_t)s2 * 32 + lane];
        float v3 = g_p[(size_t)s3 * 32 + lane];
        acc += (v0 + v1) + (v2 + v3);
    }
    for (; e < eend; e++) {
        acc += g_p[(size_t)g_csrc[e] * 32 + lane];
    }
    float inv = 1.f / (float)(deg > 0 ? deg : 1);
    size_t o = (size_t)n * 32 + lane;
    out[o] = fmaf(acc, inv, g_q[o]);
}

// ---------------- launch ----------------
extern "C" void kernel_launch(void* const* d_in, const int* in_sizes, int n_in,
                              void* d_out, int out_size) {
    // Bind inputs BY ELEMENT COUNT (robust to metadata ordering).
    const float* x   = nullptr;   // 6,400,000
    const int*   ei  = nullptr;   // 2,400,000 (int32)
    const float* W1l = nullptr;   // 4096 (first)
    const float* W1r = nullptr;   // 4096 (second)
    const float* b1  = nullptr;   // 64
    const float* W2l = nullptr;   // 2048 (first)
    const float* W2r = nullptr;   // 2048 (second)
    const float* b2  = nullptr;   // 32
    for (int i = 0; i < n_in; i++) {
        int sz = in_sizes[i];
        const void* p = d_in[i];
        if      (sz == N_NODES * C_IN)   x  = (const float*)p;
        else if (sz == 2 * N_EDGES)      ei = (const int*)p;
        else if (sz == C_IN * C_HID)   { if (!W1l) W1l = (const float*)p; else W1r = (const float*)p; }
        else if (sz == C_HID)            b1 = (const float*)p;
        else if (sz == C_HID * C_OUT)  { if (!W2l) W2l = (const float*)p; else W2r = (const float*)p; }
        else if (sz == C_OUT)            b2 = (const float*)p;
    }
    float* out = (float*)d_out;
    if (!x || !ei || !W1l || !W1r || !b1 || !W2l || !W2r || !b2) return;

    int gridW = (N_NODES + 7) / 8;             // 12500 (warp-per-node, 8 warps/blk)

    // CSR build (transform1 rides along with k_fill)
    k_zero_cnt<<<GRID_N, TB>>>();
    k_count<<<GRID_E, TB>>>(ei);
    k_scan_a<<<NB, SCAN_B>>>();
    k_scan_b<<<1, 512>>>();
    k_scan_c<<<GRID_N, TB>>>();
    k_fill_t1<<<GRID_N + GRID_E, TB>>>(ei, x, W1l, W1r, b1);

    // layer 1 aggregate
    k_agg1<<<gridW, TB>>>();

    // layer 2
    k_transform2<<<GRID_N, TB>>>(W2l, W2r, b2);
    k_agg2<<<gridW, TB>>>(out);
}

// round 9
// speedup vs baseline: 1.2475x; 1.1970x over previous
#include <cuda_runtime.h>
#include <cuda_fp16.h>
#include <cstdint>

#define N_NODES 100000
#define N_EDGES 1200000
#define C_IN 64
#define C_HID 64
#define C_OUT 32

#define TB 256
#define GRID_N ((N_NODES + TB - 1) / TB)           // 391
#define GRID_E2 ((N_EDGES / 2 + TB - 1) / TB)      // 2344 (2 edges/thread)
#define GRID_E4 ((N_EDGES / 4 + TB - 1) / TB)      // 1172 (4 edges/thread)

#define TILE_ITEMS 2048
#define N_TILES ((N_NODES + TILE_ITEMS - 1) / TILE_ITEMS)   // 49

// ---------------- scratch (device globals; no allocs allowed) ----------------
__device__ int     g_rowptr[N_NODES + 1];
__device__ int     g_cursor[N_NODES];
__device__ int     g_csrc[N_EDGES];
__device__ unsigned long long g_tstate[N_TILES];   // (status<<32)|value; 1=agg,2=prefix
__device__ int     g_ticket;
__device__ __half2 g_yh[N_NODES * 32];   // x @ W1_l   (fp16, gathered by agg1)
__device__ float   g_z [N_NODES * 64];   // x @ W1_r + b1
__device__ float   g_h [N_NODES * 64];   // relu(mean(y)+z)
__device__ __half2 g_ph[N_NODES * 16];   // h @ W2_l   (fp16, gathered by agg2)
__device__ float   g_q [N_NODES * 32];   // h @ W2_r + b2

// ---------------- packed f32x2 FMA (ptxas never emits FFMA2 from C++) -------
__device__ __forceinline__ unsigned long long ffma2(unsigned long long a,
                                                    unsigned long long b,
                                                    unsigned long long c) {
    unsigned long long d;
    asm("fma.rn.f32x2 %0, %1, %2, %3;" : "=l"(d) : "l"(a), "l"(b), "l"(c));
    return d;
}
__device__ __forceinline__ float f2_sum(unsigned long long v) {
    float lo, hi;
    asm("mov.b64 {%0, %1}, %2;" : "=f"(lo), "=f"(hi) : "l"(v));
    return lo + hi;
}

// ---------------- init: zero cursor + scan state ----------------
__global__ void k_init() {
    int i = blockIdx.x * blockDim.x + threadIdx.x;
    if (i < N_NODES) g_cursor[i] = 0;
    if (i < N_TILES) g_tstate[i] = 0ull;
    if (i == 0) g_ticket = 0;
}

// ---------------- count: 4 edges/thread ----------------
__global__ void k_count(const int* __restrict__ ei) {
    int i = blockIdx.x * blockDim.x + threadIdx.x;
    if (i < N_EDGES / 4) {
        int4 d4 = ((const int4*)(ei + N_EDGES))[i];
        if ((unsigned)d4.x < (unsigned)N_NODES) atomicAdd(&g_cursor[d4.x], 1);
        if ((unsigned)d4.y < (unsigned)N_NODES) atomicAdd(&g_cursor[d4.y], 1);
        if ((unsigned)d4.z < (unsigned)N_NODES) atomicAdd(&g_cursor[d4.z], 1);
        if ((unsigned)d4.w < (unsigned)N_NODES) atomicAdd(&g_cursor[d4.w], 1);
    }
}

// ---------------- single-pass scan: decoupled lookback ----------------
// counts (g_cursor) -> exclusive prefix into g_rowptr AND g_cursor.
__global__ void __launch_bounds__(TB) k_scan() {
    __shared__ int s[2 * TB];         // padded Kogge-Stone (low half stays 0)
    __shared__ int stile;
    __shared__ int sprefix;
    int t = threadIdx.x;
    if (t == 0) stile = atomicAdd(&g_ticket, 1);
    __syncthreads();
    int tile = stile;
    int base = tile * TILE_ITEMS + t * 8;

    // load 8 items + thread-local sum
    int v[8]; int sum = 0;
    #pragma unroll
    for (int i = 0; i < 8; i++) {
        int idx = base + i;
        v[i] = (idx < N_NODES) ? g_cursor[idx] : 0;
        sum += v[i];
    }
    // block scan of per-thread sums
    s[t] = 0;
    int si = TB + t;
    s[si] = sum;
    __syncthreads();
    #pragma unroll
    for (int off = 1; off < TB; off <<= 1) {
        int x = s[si - off];
        __syncthreads();
        s[si] += x;
        __syncthreads();
    }
    int excl_thread = s[si] - sum;
    int block_total = s[2 * TB - 1];

    // publish aggregate, then lookback (warp 0)
    if (t == 0)
        atomicExch(&g_tstate[tile], (1ull << 32) | (unsigned)block_total);
    if (t < 32) {
        int prefix = 0;
        int b = tile;
        while (b > 0) {
            int look = b - 1 - t;
            unsigned long long st;
            if (look >= 0) {
                do { st = atomicAdd(&g_tstate[look], 0ull); } while ((st >> 32) == 0u);
            } else {
                st = (2ull << 32);                 // virtual prefix 0 before tile 0
            }
            unsigned status = (unsigned)(st >> 32);
            int val = (int)(st & 0xffffffffu);
            unsigned pmask = __ballot_sync(0xffffffffu, status == 2u);
            int contrib;
            if (pmask) {
                int L = __ffs(pmask) - 1;          // nearest prefix tile
                contrib = (t <= L) ? val : 0;
            } else {
                contrib = val;
            }
            #pragma unroll
            for (int o = 16; o > 0; o >>= 1)
                contrib += __shfl_xor_sync(0xffffffffu, contrib, o);
            prefix += contrib;
            if (pmask) break;
            b -= 32;
        }
        if (t == 0) {
            sprefix = prefix;
            atomicExch(&g_tstate[tile],
                       (2ull << 32) | (unsigned)(prefix + block_total));
        }
    }
    __syncthreads();

    int pfx = sprefix + excl_thread;
    #pragma unroll
    for (int i = 0; i < 8; i++) {
        int idx = base + i;
        if (idx < N_NODES) { g_rowptr[idx] = pfx; g_cursor[idx] = pfx; }
        pfx += v[i];
        if (idx == N_NODES - 1) g_rowptr[N_NODES] = pfx;
    }
}

// ---------------- fused: transform1 (blocks [0,GRID_N)) + fill (rest) -------
__global__ void __launch_bounds__(TB) k_fill_t1(const int* __restrict__ ei,
                                                const float* __restrict__ x,
                                                const float* __restrict__ Wl,
                                                const float* __restrict__ Wr,
                                                const float* __restrict__ b1) {
    __shared__ float sWl[64 * 64];   // transposed: sWl[j*64+k] = Wl[k*64+j]
    __shared__ float sWr[64 * 64];
    __shared__ float sB[64];

    int t = threadIdx.x;

    if (blockIdx.x >= GRID_N) {
        // ---- fill branch: 2 edges/thread ----
        int i = (blockIdx.x - GRID_N) * TB + t;
        if (i < N_EDGES / 2) {
            int2 s2 = ((const int2*)ei)[i];
            int2 d2 = ((const int2*)(ei + N_EDGES))[i];
            if ((unsigned)s2.x < (unsigned)N_NODES && (unsigned)d2.x < (unsigned)N_NODES) {
                int pos = atomicAdd(&g_cursor[d2.x], 1);
                if ((unsigned)pos < (unsigned)N_EDGES) g_csrc[pos] = s2.x;
            }
            if ((unsigned)s2.y < (unsigned)N_NODES && (unsigned)d2.y < (unsigned)N_NODES) {
                int pos = atomicAdd(&g_cursor[d2.y], 1);
                if ((unsigned)pos < (unsigned)N_EDGES) g_csrc[pos] = s2.y;
            }
        }
        return;
    }

    // ---- transform1 branch ----
    for (int idx = t; idx < 4096; idx += TB) {
        int k = idx >> 6, j = idx & 63;
        sWl[j * 64 + k] = Wl[idx];
        sWr[j * 64 + k] = Wr[idx];
    }
    if (t < 64) sB[t] = b1[t];
    __syncthreads();

    int n = blockIdx.x * TB + t;
    if (n >= N_NODES) return;

    unsigned long long xv[32];
    const ulonglong2* xr = (const ulonglong2*)(x + (size_t)n * 64);
    #pragma unroll
    for (int i = 0; i < 16; i++) { ulonglong2 v = xr[i]; xv[2 * i] = v.x; xv[2 * i + 1] = v.y; }

    __half2* yo = g_yh + (size_t)n * 32;
    float2*  zo = (float2*)(g_z + (size_t)n * 64);
    #pragma unroll 2
    for (int j = 0; j < 64; j += 2) {
        const ulonglong2* wl0 = (const ulonglong2*)(sWl + j * 64);
        const ulonglong2* wl1 = (const ulonglong2*)(sWl + (j + 1) * 64);
        const ulonglong2* wr0 = (const ulonglong2*)(sWr + j * 64);
        const ulonglong2* wr1 = (const ulonglong2*)(sWr + (j + 1) * 64);
        unsigned long long aL0 = 0ull, aL1 = 0ull, aR0 = 0ull, aR1 = 0ull;
        #pragma unroll
        for (int m = 0; m < 16; m++) {
            ulonglong2 a0 = wl0[m], a1 = wl1[m], c0 = wr0[m], c1 = wr1[m];
            unsigned long long x0 = xv[2 * m], x1 = xv[2 * m + 1];
            aL0 = ffma2(a0.x, x0, aL0); aL0 = ffma2(a0.y, x1, aL0);
            aL1 = ffma2(a1.x, x0, aL1); aL1 = ffma2(a1.y, x1, aL1);
            aR0 = ffma2(c0.x, x0, aR0); aR0 = ffma2(c0.y, x1, aR0);
            aR1 = ffma2(c1.x, x0, aR1); aR1 = ffma2(c1.y, x1, aR1);
        }
        yo[j >> 1] = __floats2half2_rn(f2_sum(aL0), f2_sum(aL1));
        zo[j >> 1] = make_float2(f2_sum(aR0) + sB[j], f2_sum(aR1) + sB[j + 1]);
    }
}

// ---------------- layer-1 aggregate + relu: warp per node (fp16 gather) -----
__global__ void k_agg1() {
    int n = blockIdx.x * 8 + (threadIdx.x >> 5);
    if (n >= N_NODES) return;
    int lane = threadIdx.x & 31;
    int b = g_rowptr[n], eend = g_rowptr[n + 1];
    int deg = eend - b;
    float ax = 0.f, ay = 0.f;
    int e = b;
    for (; e + 8 <= eend; e += 8) {
        int s0 = g_csrc[e],     s1 = g_csrc[e + 1], s2 = g_csrc[e + 2], s3 = g_csrc[e + 3];
        int s4 = g_csrc[e + 4], s5 = g_csrc[e + 5], s6 = g_csrc[e + 6], s7 = g_csrc[e + 7];
        float2 f0 = __half22float2(g_yh[(size_t)s0 * 32 + lane]);
        float2 f1 = __half22float2(g_yh[(size_t)s1 * 32 + lane]);
        float2 f2 = __half22float2(g_yh[(size_t)s2 * 32 + lane]);
        float2 f3 = __half22float2(g_yh[(size_t)s3 * 32 + lane]);
        float2 f4 = __half22float2(g_yh[(size_t)s4 * 32 + lane]);
        float2 f5 = __half22float2(g_yh[(size_t)s5 * 32 + lane]);
        float2 f6 = __half22float2(g_yh[(size_t)s6 * 32 + lane]);
        float2 f7 = __half22float2(g_yh[(size_t)s7 * 32 + lane]);
        ax += ((f0.x + f1.x) + (f2.x + f3.x)) + ((f4.x + f5.x) + (f6.x + f7.x));
        ay += ((f0.y + f1.y) + (f2.y + f3.y)) + ((f4.y + f5.y) + (f6.y + f7.y));
    }
    for (; e < eend; e++) {
        float2 f = __half22float2(g_yh[(size_t)g_csrc[e] * 32 + lane]);
        ax += f.x; ay += f.y;
    }
    float inv = 1.f / (float)(deg > 0 ? deg : 1);
    size_t o = (size_t)n * 64 + lane * 2;
    g_h[o]     = fmaxf(fmaf(ax, inv, g_z[o]), 0.f);
    g_h[o + 1] = fmaxf(fmaf(ay, inv, g_z[o + 1]), 0.f);
}

// ---------------- layer-2 transform: p(fp16) = h@W2_l, q = h@W2_r + b2 ------
__global__ void __launch_bounds__(TB) k_transform2(const float* __restrict__ Wl,
                                                   const float* __restrict__ Wr,
                                                   const float* __restrict__ b2) {
    __shared__ float sWl[32 * 64];   // sWl[j*64+k] = Wl[k*32+j]
    __shared__ float sWr[32 * 64];
    __shared__ float sB[32];
    int t = threadIdx.x;
    for (int idx = t; idx < 2048; idx += TB) {
        int k = idx >> 5, j = idx & 31;
        sWl[j * 64 + k] = Wl[idx];
        sWr[j * 64 + k] = Wr[idx];
    }
    if (t < 32) sB[t] = b2[t];
    __syncthreads();

    int n = blockIdx.x * TB + t;
    if (n >= N_NODES) return;

    unsigned long long hv[32];
    const ulonglong2* hr = (const ulonglong2*)(g_h + (size_t)n * 64);
    #pragma unroll
    for (int i = 0; i < 16; i++) { ulonglong2 v = hr[i]; hv[2 * i] = v.x; hv[2 * i + 1] = v.y; }

    __half2* po = g_ph + (size_t)n * 16;
    float2*  qo = (float2*)(g_q + (size_t)n * 32);
    #pragma unroll 2
    for (int j = 0; j < 32; j += 2) {
        const ulonglong2* wl0 = (const ulonglong2*)(sWl + j * 64);
        const ulonglong2* wl1 = (const ulonglong2*)(sWl + (j + 1) * 64);
        const ulonglong2* wr0 = (const ulonglong2*)(sWr + j * 64);
        const ulonglong2* wr1 = (const ulonglong2*)(sWr + (j + 1) * 64);
        unsigned long long aL0 = 0ull, aL1 = 0ull, aR0 = 0ull, aR1 = 0ull;
        #pragma unroll
        for (int m = 0; m < 16; m++) {
            ulonglong2 a0 = wl0[m], a1 = wl1[m], c0 = wr0[m], c1 = wr1[m];
            unsigned long long x0 = hv[2 * m], x1 = hv[2 * m + 1];
            aL0 = ffma2(a0.x, x0, aL0); aL0 = ffma2(a0.y, x1, aL0);
            aL1 = ffma2(a1.x, x0, aL1); aL1 = ffma2(a1.y, x1, aL1);
            aR0 = ffma2(c0.x, x0, aR0); aR0 = ffma2(c0.y, x1, aR0);
            aR1 = ffma2(c1.x, x0, aR1); aR1 = ffma2(c1.y, x1, aR1);
        }
        po[j >> 1] = __floats2half2_rn(f2_sum(aL0), f2_sum(aL1));
        qo[j >> 1] = make_float2(f2_sum(aR0) + sB[j], f2_sum(aR1) + sB[j + 1]);
    }
}

// ---------------- layer-2 aggregate -> output (2 edges per warp) ------------
__global__ void k_agg2(float* __restrict__ out) {
    int n = blockIdx.x * 8 + (threadIdx.x >> 5);
    if (n >= N_NODES) return;
    int lane = threadIdx.x & 31;
    int half = lane >> 4;       // 0: even edge, 1: odd edge
    int sub  = lane & 15;       // half2 index within row (16 * half2 = 32 ch)
    int b = g_rowptr[n], eend = g_rowptr[n + 1];
    int deg = eend - b;
    float ax = 0.f, ay = 0.f;
    int e = b;
    #pragma unroll 2
    for (; e + 2 <= eend; e += 2) {
        int s = g_csrc[e + half];
        float2 f = __half22float2(g_ph[(size_t)s * 16 + sub]);
        ax += f.x; ay += f.y;
    }
    if (e < eend && half == 0) {
        float2 f = __half22float2(g_ph[(size_t)g_csrc[e] * 16 + sub]);
        ax += f.x; ay += f.y;
    }
    // combine the two edge-halves
    ax += __shfl_xor_sync(0xffffffffu, ax, 16);
    ay += __shfl_xor_sync(0xffffffffu, ay, 16);
    if (half == 0) {
        float inv = 1.f / (float)(deg > 0 ? deg : 1);
        size_t o = (size_t)n * 32 + sub * 2;
        out[o]     = fmaf(ax, inv, g_q[o]);
        out[o + 1] = fmaf(ay, inv, g_q[o + 1]);
    }
}

// ---------------- launch ----------------
extern "C" void kernel_launch(void* const* d_in, const int* in_sizes, int n_in,
                              void* d_out, int out_size) {
    // Bind inputs BY ELEMENT COUNT (robust to metadata ordering).
    const float* x   = nullptr;   // 6,400,000
    const int*   ei  = nullptr;   // 2,400,000 (int32)
    const float* W1l = nullptr;   // 4096 (first)
    const float* W1r = nullptr;   // 4096 (second)
    const float* b1  = nullptr;   // 64
    const float* W2l = nullptr;   // 2048 (first)
    const float* W2r = nullptr;   // 2048 (second)
    const float* b2  = nullptr;   // 32
    for (int i = 0; i < n_in; i++) {
        int sz = in_sizes[i];
        const void* p = d_in[i];
        if      (sz == N_NODES * C_IN)   x  = (const float*)p;
        else if (sz == 2 * N_EDGES)      ei = (const int*)p;
        else if (sz == C_IN * C_HID)   { if (!W1l) W1l = (const float*)p; else W1r = (const float*)p; }
        else if (sz == C_HID)            b1 = (const float*)p;
        else if (sz == C_HID * C_OUT)  { if (!W2l) W2l = (const float*)p; else W2r = (const float*)p; }
        else if (sz == C_OUT)            b2 = (const float*)p;
    }
    float* out = (float*)d_out;
    if (!x || !ei || !W1l || !W1r || !b1 || !W2l || !W2r || !b2) return;

    int gridW = (N_NODES + 7) / 8;             // 12500 (warp-per-node, 8 warps/blk)

    k_init<<<GRID_N, TB>>>();
    k_count<<<GRID_E4, TB>>>(ei);
    k_scan<<<N_TILES, TB>>>();
    k_fill_t1<<<GRID_N + GRID_E2, TB>>>(ei, x, W1l, W1r, b1);

    k_agg1<<<gridW, TB>>>();

    k_transform2<<<GRID_N, TB>>>(W2l, W2r, b2);
    k_agg2<<<gridW, TB>>>(out);
}

// round 10
// speedup vs baseline: 1.5216x; 1.2197x over previous
#include <cuda_runtime.h>
#include <cuda_fp16.h>
#include <cstdint>

#define N_NODES 100000
#define N_EDGES 1200000
#define C_IN 64
#define C_HID 64
#define C_OUT 32

#define TB 256
#define GRID_N ((N_NODES + TB - 1) / TB)           // 391
#define GRID_E2 ((N_EDGES / 2 + TB - 1) / TB)      // 2344 (2 edges/thread)
#define GRID_E4 ((N_EDGES / 4 + TB - 1) / TB)      // 1172 (4 edges/thread)

#define T_TILE 64
#define GRID_T ((N_NODES + T_TILE - 1) / T_TILE)   // 1563

#define TILE_ITEMS 2048
#define N_TILES ((N_NODES + TILE_ITEMS - 1) / TILE_ITEMS)   // 49

// ---------------- scratch (device globals; no allocs allowed) ----------------
__device__ int     g_rowptr[N_NODES + 1];
__device__ int     g_cursor[N_NODES];
__device__ int     g_csrc[N_EDGES];
__device__ unsigned long long g_tstate[N_TILES];   // (status<<32)|value; 1=agg,2=prefix
__device__ int     g_ticket;
__device__ __half2 g_yh[N_NODES * 32];   // x @ W1_l   (fp16, gathered by agg1)
__device__ float   g_z [N_NODES * 64];   // x @ W1_r + b1
__device__ float   g_h [N_NODES * 64];   // relu(mean(y)+z)
__device__ __half2 g_ph[N_NODES * 16];   // h @ W2_l   (fp16, gathered by agg2)
__device__ float   g_q [N_NODES * 32];   // h @ W2_r + b2

// ---------------- packed f32x2 helpers ----------------
__device__ __forceinline__ unsigned long long ffma2(unsigned long long a,
                                                    unsigned long long b,
                                                    unsigned long long c) {
    unsigned long long d;
    asm("fma.rn.f32x2 %0, %1, %2, %3;" : "=l"(d) : "l"(a), "l"(b), "l"(c));
    return d;
}
__device__ __forceinline__ unsigned long long packdup(float v) {
    unsigned long long r;
    asm("mov.b64 %0, {%1, %1};" : "=l"(r) : "f"(v));
    return r;
}
__device__ __forceinline__ float2 unpack2(unsigned long long v) {
    float2 r;
    asm("mov.b64 {%0, %1}, %2;" : "=f"(r.x), "=f"(r.y) : "l"(v));
    return r;
}

// ---------------- init: zero cursor + scan state ----------------
__global__ void k_init() {
    int i = blockIdx.x * blockDim.x + threadIdx.x;
    if (i < N_NODES) g_cursor[i] = 0;
    if (i < N_TILES) g_tstate[i] = 0ull;
    if (i == 0) g_ticket = 0;
}

// ---------------- count: 4 edges/thread ----------------
__global__ void k_count(const int* __restrict__ ei) {
    int i = blockIdx.x * blockDim.x + threadIdx.x;
    if (i < N_EDGES / 4) {
        int4 d4 = ((const int4*)(ei + N_EDGES))[i];
        if ((unsigned)d4.x < (unsigned)N_NODES) atomicAdd(&g_cursor[d4.x], 1);
        if ((unsigned)d4.y < (unsigned)N_NODES) atomicAdd(&g_cursor[d4.y], 1);
        if ((unsigned)d4.z < (unsigned)N_NODES) atomicAdd(&g_cursor[d4.z], 1);
        if ((unsigned)d4.w < (unsigned)N_NODES) atomicAdd(&g_cursor[d4.w], 1);
    }
}

// ---------------- single-pass scan: decoupled lookback ----------------
__global__ void __launch_bounds__(TB) k_scan() {
    __shared__ int s[2 * TB];
    __shared__ int stile;
    __shared__ int sprefix;
    int t = threadIdx.x;
    if (t == 0) stile = atomicAdd(&g_ticket, 1);
    __syncthreads();
    int tile = stile;
    int base = tile * TILE_ITEMS + t * 8;

    int v[8]; int sum = 0;
    #pragma unroll
    for (int i = 0; i < 8; i++) {
        int idx = base + i;
        v[i] = (idx < N_NODES) ? g_cursor[idx] : 0;
        sum += v[i];
    }
    s[t] = 0;
    int si = TB + t;
    s[si] = sum;
    __syncthreads();
    #pragma unroll
    for (int off = 1; off < TB; off <<= 1) {
        int x = s[si - off];
        __syncthreads();
        s[si] += x;
        __syncthreads();
    }
    int excl_thread = s[si] - sum;
    int block_total = s[2 * TB - 1];

    if (t == 0)
        atomicExch(&g_tstate[tile], (1ull << 32) | (unsigned)block_total);
    if (t < 32) {
        int prefix = 0;
        int b = tile;
        while (b > 0) {
            int look = b - 1 - t;
            unsigned long long st;
            if (look >= 0) {
                do { st = atomicAdd(&g_tstate[look], 0ull); } while ((st >> 32) == 0u);
            } else {
                st = (2ull << 32);
            }
            unsigned status = (unsigned)(st >> 32);
            int val = (int)(st & 0xffffffffu);
            unsigned pmask = __ballot_sync(0xffffffffu, status == 2u);
            int contrib;
            if (pmask) {
                int L = __ffs(pmask) - 1;
                contrib = (t <= L) ? val : 0;
            } else {
                contrib = val;
            }
            #pragma unroll
            for (int o = 16; o > 0; o >>= 1)
                contrib += __shfl_xor_sync(0xffffffffu, contrib, o);
            prefix += contrib;
            if (pmask) break;
            b -= 32;
        }
        if (t == 0) {
            sprefix = prefix;
            atomicExch(&g_tstate[tile],
                       (2ull << 32) | (unsigned)(prefix + block_total));
        }
    }
    __syncthreads();

    int pfx = sprefix + excl_thread;
    #pragma unroll
    for (int i = 0; i < 8; i++) {
        int idx = base + i;
        if (idx < N_NODES) { g_rowptr[idx] = pfx; g_cursor[idx] = pfx; }
        pfx += v[i];
        if (idx == N_NODES - 1) g_rowptr[N_NODES] = pfx;
    }
}

// ---------------- fused: tiled transform1 (blocks [0,GRID_T)) + fill --------
// Tiled GEMM: block = 64 nodes x 128 outputs (j<64: y->fp16, j>=64: z=.+b1).
// sX[k][node] transposed (conflict-free: lane==node on store, float2 on load).
// Warp layout: ty=tid&31 -> 2 nodes, tx=tid>>5 -> 16 outputs (W reads are
// warp-uniform => pure LDS broadcast). FMA-bound by construction.
__global__ void __launch_bounds__(TB) k_fill_t1(const int* __restrict__ ei,
                                                const float* __restrict__ x,
                                                const float* __restrict__ Wl,
                                                const float* __restrict__ Wr,
                                                const float* __restrict__ b1) {
    __shared__ float sX[64 * 64];    // [k][node]
    __shared__ float sW[64 * 128];   // [k][j]  j<64 -> W1_l, j>=64 -> W1_r
    __shared__ float sB[64];

    int t = threadIdx.x;

    if (blockIdx.x >= GRID_T) {
        // ---- fill branch: 2 edges/thread ----
        int i = (blockIdx.x - GRID_T) * TB + t;
        if (i < N_EDGES / 2) {
            int2 s2 = ((const int2*)ei)[i];
            int2 d2 = ((const int2*)(ei + N_EDGES))[i];
            if ((unsigned)s2.x < (unsigned)N_NODES && (unsigned)d2.x < (unsigned)N_NODES) {
                int pos = atomicAdd(&g_cursor[d2.x], 1);
                if ((unsigned)pos < (unsigned)N_EDGES) g_csrc[pos] = s2.x;
            }
            if ((unsigned)s2.y < (unsigned)N_NODES && (unsigned)d2.y < (unsigned)N_NODES) {
                int pos = atomicAdd(&g_cursor[d2.y], 1);
                if ((unsigned)pos < (unsigned)N_EDGES) g_csrc[pos] = s2.y;
            }
        }
        return;
    }

    int nbase = blockIdx.x * T_TILE;

    // stage weights [k][128]
    for (int idx = t; idx < 8192; idx += TB) {
        int k = idx >> 7, j = idx & 127;
        sW[idx] = (j < 64) ? Wl[k * 64 + j] : Wr[k * 64 + (j - 64)];
    }
    if (t < 64) sB[t] = b1[t];

    // stage x transposed: thread (node=t&63, kq=t>>6) covers k in [kq*16, kq*16+16)
    {
        int node = t & 63, kq = t >> 6;
        int ng = nbase + node;
        const float4* xr = (const float4*)(x + (size_t)ng * 64 + kq * 16);
        #pragma unroll
        for (int i = 0; i < 4; i++) {
            float4 v = (ng < N_NODES) ? xr[i] : make_float4(0.f, 0.f, 0.f, 0.f);
            int k0 = kq * 16 + i * 4;
            sX[(k0 + 0) * 64 + node] = v.x;
            sX[(k0 + 1) * 64 + node] = v.y;
            sX[(k0 + 2) * 64 + node] = v.z;
            sX[(k0 + 3) * 64 + node] = v.w;
        }
    }
    __syncthreads();

    int ty = t & 31;          // 2 nodes: 2*ty, 2*ty+1
    int tx = t >> 5;          // 16 outputs: j0 = 16*tx
    const float2*      sX2 = (const float2*)sX;        // row = 32 float2
    const ulonglong2*  sWu = (const ulonglong2*)sW;    // row = 32 ulonglong2

    unsigned long long acc[16];
    #pragma unroll
    for (int i = 0; i < 16; i++) acc[i] = 0ull;

    #pragma unroll 4
    for (int k = 0; k < 64; k++) {
        float2 xv = sX2[k * 32 + ty];
        unsigned long long d0 = packdup(xv.x);
        unsigned long long d1 = packdup(xv.y);
        ulonglong2 w0 = sWu[k * 32 + tx * 4 + 0];
        ulonglong2 w1 = sWu[k * 32 + tx * 4 + 1];
        ulonglong2 w2 = sWu[k * 32 + tx * 4 + 2];
        ulonglong2 w3 = sWu[k * 32 + tx * 4 + 3];
        acc[0]  = ffma2(w0.x, d0, acc[0]);  acc[1]  = ffma2(w0.y, d0, acc[1]);
        acc[2]  = ffma2(w1.x, d0, acc[2]);  acc[3]  = ffma2(w1.y, d0, acc[3]);
        acc[4]  = ffma2(w2.x, d0, acc[4]);  acc[5]  = ffma2(w2.y, d0, acc[5]);
        acc[6]  = ffma2(w3.x, d0, acc[6]);  acc[7]  = ffma2(w3.y, d0, acc[7]);
        acc[8]  = ffma2(w0.x, d1, acc[8]);  acc[9]  = ffma2(w0.y, d1, acc[9]);
        acc[10] = ffma2(w1.x, d1, acc[10]); acc[11] = ffma2(w1.y, d1, acc[11]);
        acc[12] = ffma2(w2.x, d1, acc[12]); acc[13] = ffma2(w2.y, d1, acc[13]);
        acc[14] = ffma2(w3.x, d1, acc[14]); acc[15] = ffma2(w3.y, d1, acc[15]);
    }

    int j0 = tx * 16;
    #pragma unroll
    for (int nn = 0; nn < 2; nn++) {
        int n = nbase + ty * 2 + nn;
        if (n >= N_NODES) break;
        const unsigned long long* a = acc + nn * 8;
        if (tx < 4) {
            // y -> fp16: 8 half2 = 2x 16B stores at g_yh[n*32 + j0/2]
            __half2 hh[8];
            #pragma unroll
            for (int jp = 0; jp < 8; jp++) {
                float2 f = unpack2(a[jp]);
                hh[jp] = __floats2half2_rn(f.x, f.y);
            }
            uint4* dst = (uint4*)(g_yh + (size_t)n * 32 + (j0 >> 1));
            dst[0] = *(uint4*)(hh);
            dst[1] = *(uint4*)(hh + 4);
        } else {
            // z = . + b1 : 16 floats = 4x float4 at g_z[n*64 + (j0-64)]
            float vz[16];
            #pragma unroll
            for (int jp = 0; jp < 8; jp++) {
                float2 f = unpack2(a[jp]);
                vz[2 * jp]     = f.x + sB[j0 - 64 + 2 * jp];
                vz[2 * jp + 1] = f.y + sB[j0 - 64 + 2 * jp + 1];
            }
            float4* dst = (float4*)(g_z + (size_t)n * 64 + (j0 - 64));
            #pragma unroll
            for (int i = 0; i < 4; i++) dst[i] = *(float4*)(vz + 4 * i);
        }
    }
}

// ---------------- layer-1 aggregate + relu: warp per node (fp16 gather) -----
__global__ void k_agg1() {
    int n = blockIdx.x * 8 + (threadIdx.x >> 5);
    if (n >= N_NODES) return;
    int lane = threadIdx.x & 31;
    int b = g_rowptr[n], eend = g_rowptr[n + 1];
    int deg = eend - b;
    float ax = 0.f, ay = 0.f;
    int e = b;
    for (; e + 8 <= eend; e += 8) {
        int s0 = g_csrc[e],     s1 = g_csrc[e + 1], s2 = g_csrc[e + 2], s3 = g_csrc[e + 3];
        int s4 = g_csrc[e + 4], s5 = g_csrc[e + 5], s6 = g_csrc[e + 6], s7 = g_csrc[e + 7];
        float2 f0 = __half22float2(g_yh[(size_t)s0 * 32 + lane]);
        float2 f1 = __half22float2(g_yh[(size_t)s1 * 32 + lane]);
        float2 f2 = __half22float2(g_yh[(size_t)s2 * 32 + lane]);
        float2 f3 = __half22float2(g_yh[(size_t)s3 * 32 + lane]);
        float2 f4 = __half22float2(g_yh[(size_t)s4 * 32 + lane]);
        float2 f5 = __half22float2(g_yh[(size_t)s5 * 32 + lane]);
        float2 f6 = __half22float2(g_yh[(size_t)s6 * 32 + lane]);
        float2 f7 = __half22float2(g_yh[(size_t)s7 * 32 + lane]);
        ax += ((f0.x + f1.x) + (f2.x + f3.x)) + ((f4.x + f5.x) + (f6.x + f7.x));
        ay += ((f0.y + f1.y) + (f2.y + f3.y)) + ((f4.y + f5.y) + (f6.y + f7.y));
    }
    for (; e < eend; e++) {
        float2 f = __half22float2(g_yh[(size_t)g_csrc[e] * 32 + lane]);
        ax += f.x; ay += f.y;
    }
    float inv = 1.f / (float)(deg > 0 ? deg : 1);
    size_t o = (size_t)n * 64 + lane * 2;
    g_h[o]     = fmaxf(fmaf(ax, inv, g_z[o]), 0.f);
    g_h[o + 1] = fmaxf(fmaf(ay, inv, g_z[o + 1]), 0.f);
}

// ---------------- layer-2 transform (tiled): p(fp16), q = .+b2 --------------
// block = 64 nodes x 64 outputs; ty=tid&31 -> 2 nodes, tx=tid>>5 -> 8 outputs.
__global__ void __launch_bounds__(TB) k_transform2(const float* __restrict__ Wl,
                                                   const float* __restrict__ Wr,
                                                   const float* __restrict__ b2) {
    __shared__ float sH[64 * 64];    // [k][node]
    __shared__ float sW[64 * 64];    // [k][j]  j<32 -> W2_l, j>=32 -> W2_r
    __shared__ float sB[32];

    int t = threadIdx.x;
    int nbase = blockIdx.x * T_TILE;

    for (int idx = t; idx < 4096; idx += TB) {
        int k = idx >> 6, j = idx & 63;
        sW[idx] = (j < 32) ? Wl[k * 32 + j] : Wr[k * 32 + (j - 32)];
    }
    if (t < 32) sB[t] = b2[t];

    {
        int node = t & 63, kq = t >> 6;
        int ng = nbase + node;
        const float4* hr = (const float4*)(g_h + (size_t)ng * 64 + kq * 16);
        #pragma unroll
        for (int i = 0; i < 4; i++) {
            float4 v = (ng < N_NODES) ? hr[i] : make_float4(0.f, 0.f, 0.f, 0.f);
            int k0 = kq * 16 + i * 4;
            sH[(k0 + 0) * 64 + node] = v.x;
            sH[(k0 + 1) * 64 + node] = v.y;
            sH[(k0 + 2) * 64 + node] = v.z;
            sH[(k0 + 3) * 64 + node] = v.w;
        }
    }
    __syncthreads();

    int ty = t & 31;
    int tx = t >> 5;          // 8 outputs: j0 = 8*tx
    const float2*     sH2 = (const float2*)sH;       // row = 32 float2
    const ulonglong2* sWu = (const ulonglong2*)sW;   // row = 16 ulonglong2

    unsigned long long acc[8];
    #pragma unroll
    for (int i = 0; i < 8; i++) acc[i] = 0ull;

    #pragma unroll 4
    for (int k = 0; k < 64; k++) {
        float2 xv = sH2[k * 32 + ty];
        unsigned long long d0 = packdup(xv.x);
        unsigned long long d1 = packdup(xv.y);
        ulonglong2 w0 = sWu[k * 16 + tx * 2 + 0];
        ulonglong2 w1 = sWu[k * 16 + tx * 2 + 1];
        acc[0] = ffma2(w0.x, d0, acc[0]);  acc[1] = ffma2(w0.y, d0, acc[1]);
        acc[2] = ffma2(w1.x, d0, acc[2]);  acc[3] = ffma2(w1.y, d0, acc[3]);
        acc[4] = ffma2(w0.x, d1, acc[4]);  acc[5] = ffma2(w0.y, d1, acc[5]);
        acc[6] = ffma2(w1.x, d1, acc[6]);  acc[7] = ffma2(w1.y, d1, acc[7]);
    }

    int j0 = tx * 8;
    #pragma unroll
    for (int nn = 0; nn < 2; nn++) {
        int n = nbase + ty * 2 + nn;
        if (n >= N_NODES) break;
        const unsigned long long* a = acc + nn * 4;
        if (tx < 4) {
            // p -> fp16: 4 half2 = 1x 16B store at g_ph[n*16 + j0/2]
            __half2 hh[4];
            #pragma unroll
            for (int jp = 0; jp < 4; jp++) {
                float2 f = unpack2(a[jp]);
                hh[jp] = __floats2half2_rn(f.x, f.y);
            }
            *(uint4*)(g_ph + (size_t)n * 16 + (j0 >> 1)) = *(uint4*)hh;
        } else {
            // q = . + b2 : 8 floats = 2x float4 at g_q[n*32 + (j0-32)]
            float vq[8];
            #pragma unroll
            for (int jp = 0; jp < 4; jp++) {
                float2 f = unpack2(a[jp]);
                vq[2 * jp]     = f.x + sB[j0 - 32 + 2 * jp];
                vq[2 * jp + 1] = f.y + sB[j0 - 32 + 2 * jp + 1];
            }
            float4* dst = (float4*)(g_q + (size_t)n * 32 + (j0 - 32));
            dst[0] = *(float4*)(vq);
            dst[1] = *(float4*)(vq + 4);
        }
    }
}

// ---------------- layer-2 aggregate -> output (2 edges per warp) ------------
__global__ void k_agg2(float* __restrict__ out) {
    int n = blockIdx.x * 8 + (threadIdx.x >> 5);
    if (n >= N_NODES) return;
    int lane = threadIdx.x & 31;
    int half = lane >> 4;
    int sub  = lane & 15;
    int b = g_rowptr[n], eend = g_rowptr[n + 1];
    int deg = eend - b;
    float ax = 0.f, ay = 0.f;
    int e = b;
    #pragma unroll 2
    for (; e + 2 <= eend; e += 2) {
        int s = g_csrc[e + half];
        float2 f = __half22float2(g_ph[(size_t)s * 16 + sub]);
        ax += f.x; ay += f.y;
    }
    if (e < eend && half == 0) {
        float2 f = __half22float2(g_ph[(size_t)g_csrc[e] * 16 + sub]);
        ax += f.x; ay += f.y;
    }
    ax += __shfl_xor_sync(0xffffffffu, ax, 16);
    ay += __shfl_xor_sync(0xffffffffu, ay, 16);
    if (half == 0) {
        float inv = 1.f / (float)(deg > 0 ? deg : 1);
        size_t o = (size_t)n * 32 + sub * 2;
        out[o]     = fmaf(ax, inv, g_q[o]);
        out[o + 1] = fmaf(ay, inv, g_q[o + 1]);
    }
}

// ---------------- launch ----------------
extern "C" void kernel_launch(void* const* d_in, const int* in_sizes, int n_in,
                              void* d_out, int out_size) {
    const float* x   = nullptr;
    const int*   ei  = nullptr;
    const float* W1l = nullptr;
    const float* W1r = nullptr;
    const float* b1  = nullptr;
    const float* W2l = nullptr;
    const float* W2r = nullptr;
    const float* b2  = nullptr;
    for (int i = 0; i < n_in; i++) {
        int sz = in_sizes[i];
        const void* p = d_in[i];
        if      (sz == N_NODES * C_IN)   x  = (const float*)p;
        else if (sz == 2 * N_EDGES)      ei = (const int*)p;
        else if (sz == C_IN * C_HID)   { if (!W1l) W1l = (const float*)p; else W1r = (const float*)p; }
        else if (sz == C_HID)            b1 = (const float*)p;
        else if (sz == C_HID * C_OUT)  { if (!W2l) W2l = (const float*)p; else W2r = (const float*)p; }
        else if (sz == C_OUT)            b2 = (const float*)p;
    }
    float* out = (float*)d_out;
    if (!x || !ei || !W1l || !W1r || !b1 || !W2l || !W2r || !b2) return;

    int gridW = (N_NODES + 7) / 8;             // 12500 (warp-per-node, 8 warps/blk)

    k_init<<<GRID_N, TB>>>();
    k_count<<<GRID_E4, TB>>>(ei);
    k_scan<<<N_TILES, TB>>>();
    k_fill_t1<<<GRID_T + GRID_E2, TB>>>(ei, x, W1l, W1r, b1);

    k_agg1<<<gridW, TB>>>();

    k_transform2<<<GRID_T, TB>>>(W2l, W2r, b2);
    k_agg2<<<gridW, TB>>>(out);
}

// round 11
// speedup vs baseline: 1.5921x; 1.0464x over previous
#include <cuda_runtime.h>
#include <cuda_fp16.h>
#include <cstdint>

#define N_NODES 100000
#define N_EDGES 1200000
#define C_IN 64
#define C_HID 64
#define C_OUT 32

#define TB 256
#define GRID_N ((N_NODES + TB - 1) / TB)           // 391
#define GRID_E2 ((N_EDGES / 2 + TB - 1) / TB)      // 2344 (2 edges/thread)
#define GRID_E4 ((N_EDGES / 4 + TB - 1) / TB)      // 1172 (4 edges/thread)

#define T_TILE 64
#define GRID_T ((N_NODES + T_TILE - 1) / T_TILE)   // 1563

#define TILE_ITEMS 2048
#define N_TILES ((N_NODES + TILE_ITEMS - 1) / TILE_ITEMS)   // 49

// ---------------- scratch (device globals; no allocs allowed) ----------------
__device__ int     g_rowptr[N_NODES + 1];
__device__ int     g_cursor[N_NODES];
__device__ int     g_csrc[N_EDGES];
__device__ unsigned long long g_tstate[N_TILES];   // (status<<32)|value; 1=agg,2=prefix
__device__ int     g_ticket;
__device__ __half2 g_yh[N_NODES * 32];   // x @ W1_l   (fp16, gathered by agg1)
__device__ float   g_z [N_NODES * 64];   // x @ W1_r + b1
__device__ float   g_h [N_NODES * 64];   // relu(mean(y)+z)
__device__ __half2 g_ph[N_NODES * 16];   // h @ W2_l   (fp16, gathered by agg2)
__device__ float   g_q [N_NODES * 32];   // h @ W2_r + b2

// ---------------- packed f32x2 helpers ----------------
__device__ __forceinline__ unsigned long long ffma2(unsigned long long a,
                                                    unsigned long long b,
                                                    unsigned long long c) {
    unsigned long long d;
    asm("fma.rn.f32x2 %0, %1, %2, %3;" : "=l"(d) : "l"(a), "l"(b), "l"(c));
    return d;
}
__device__ __forceinline__ unsigned long long packdup(float v) {
    unsigned long long r;
    asm("mov.b64 %0, {%1, %1};" : "=l"(r) : "f"(v));
    return r;
}
__device__ __forceinline__ float2 unpack2(unsigned long long v) {
    float2 r;
    asm("mov.b64 {%0, %1}, %2;" : "=f"(r.x), "=f"(r.y) : "l"(v));
    return r;
}

// ---------------- init: zero cursor + scan state ----------------
__global__ void k_init() {
    int i = blockIdx.x * blockDim.x + threadIdx.x;
    if (i < N_NODES) g_cursor[i] = 0;
    if (i < N_TILES) g_tstate[i] = 0ull;
    if (i == 0) g_ticket = 0;
}

// ---------------- fused: tiled transform1 (blocks [0,GRID_T)) + count -------
// GEMM tile: 64 nodes x 128 outputs. Thread: ty=t&15 -> 4 nodes (one float4
// LDS), tx=t>>4 -> 8 outputs (2x LDS.128). Software-pipelined k-loop: k+1
// loads issued before k's FFMA2s so the 29-cyc LDS latency is covered.
__global__ void __launch_bounds__(TB, 3) k_count_t1(const int* __restrict__ ei,
                                                    const float* __restrict__ x,
                                                    const float* __restrict__ Wl,
                                                    const float* __restrict__ Wr,
                                                    const float* __restrict__ b1) {
    __shared__ float sX[64 * 64];    // [k][node]
    __shared__ float sW[64 * 128];   // [k][j]  j<64 -> W1_l, j>=64 -> W1_r
    __shared__ float sB[64];

    int t = threadIdx.x;

    if (blockIdx.x >= GRID_T) {
        // ---- count branch: 4 edges/thread ----
        int i = (blockIdx.x - GRID_T) * TB + t;
        if (i < N_EDGES / 4) {
            int4 d4 = ((const int4*)(ei + N_EDGES))[i];
            if ((unsigned)d4.x < (unsigned)N_NODES) atomicAdd(&g_cursor[d4.x], 1);
            if ((unsigned)d4.y < (unsigned)N_NODES) atomicAdd(&g_cursor[d4.y], 1);
            if ((unsigned)d4.z < (unsigned)N_NODES) atomicAdd(&g_cursor[d4.z], 1);
            if ((unsigned)d4.w < (unsigned)N_NODES) atomicAdd(&g_cursor[d4.w], 1);
        }
        return;
    }

    int nbase = blockIdx.x * T_TILE;

    // stage weights [k][128]
    for (int idx = t; idx < 8192; idx += TB) {
        int k = idx >> 7, j = idx & 127;
        sW[idx] = (j < 64) ? Wl[k * 64 + j] : Wr[k * 64 + (j - 64)];
    }
    if (t < 64) sB[t] = b1[t];

    // stage x transposed [k][node]
    {
        int node = t & 63, kq = t >> 6;
        int ng = nbase + node;
        const float4* xr = (const float4*)(x + (size_t)ng * 64 + kq * 16);
        #pragma unroll
        for (int i = 0; i < 4; i++) {
            float4 v = (ng < N_NODES) ? xr[i] : make_float4(0.f, 0.f, 0.f, 0.f);
            int k0 = kq * 16 + i * 4;
            sX[(k0 + 0) * 64 + node] = v.x;
            sX[(k0 + 1) * 64 + node] = v.y;
            sX[(k0 + 2) * 64 + node] = v.z;
            sX[(k0 + 3) * 64 + node] = v.w;
        }
    }
    __syncthreads();

    int ty = t & 15;          // 4 nodes: 4*ty .. 4*ty+3
    int tx = t >> 4;          // 16 groups x 8 outputs: j0 = 8*tx
    const float4*     sX4 = (const float4*)sX;       // row = 16 float4
    const ulonglong2* sWu = (const ulonglong2*)sW;   // row = 32 ulonglong2

    unsigned long long acc[16];   // [node][jpair]: acc[nn*4+jp]
    #pragma unroll
    for (int i = 0; i < 16; i++) acc[i] = 0ull;

    // software pipeline: prefetch k+1 while computing k
    float4     xc = sX4[ty];
    ulonglong2 wa = sWu[tx * 2 + 0];
    ulonglong2 wb = sWu[tx * 2 + 1];
    #pragma unroll 8
    for (int k = 0; k < 64; k++) {
        float4 xn; ulonglong2 wan, wbn;
        if (k < 63) {
            xn  = sX4[(k + 1) * 16 + ty];
            wan = sWu[(k + 1) * 32 + tx * 2 + 0];
            wbn = sWu[(k + 1) * 32 + tx * 2 + 1];
        }
        unsigned long long d0 = packdup(xc.x), d1 = packdup(xc.y);
        unsigned long long d2 = packdup(xc.z), d3 = packdup(xc.w);
        acc[0]  = ffma2(wa.x, d0, acc[0]);  acc[1]  = ffma2(wa.y, d0, acc[1]);
        acc[2]  = ffma2(wb.x, d0, acc[2]);  acc[3]  = ffma2(wb.y, d0, acc[3]);
        acc[4]  = ffma2(wa.x, d1, acc[4]);  acc[5]  = ffma2(wa.y, d1, acc[5]);
        acc[6]  = ffma2(wb.x, d1, acc[6]);  acc[7]  = ffma2(wb.y, d1, acc[7]);
        acc[8]  = ffma2(wa.x, d2, acc[8]);  acc[9]  = ffma2(wa.y, d2, acc[9]);
        acc[10] = ffma2(wb.x, d2, acc[10]); acc[11] = ffma2(wb.y, d2, acc[11]);
        acc[12] = ffma2(wa.x, d3, acc[12]); acc[13] = ffma2(wa.y, d3, acc[13]);
        acc[14] = ffma2(wb.x, d3, acc[14]); acc[15] = ffma2(wb.y, d3, acc[15]);
        xc = xn; wa = wan; wb = wbn;
    }

    int j0 = tx * 8;
    #pragma unroll
    for (int nn = 0; nn < 4; nn++) {
        int n = nbase + ty * 4 + nn;
        if (n >= N_NODES) break;
        const unsigned long long* a = acc + nn * 4;
        if (tx < 8) {
            // y -> fp16: 8 outputs = 4 half2 = one 16B store
            __half2 hh[4];
            #pragma unroll
            for (int jp = 0; jp < 4; jp++) {
                float2 f = unpack2(a[jp]);
                hh[jp] = __floats2half2_rn(f.x, f.y);
            }
            *(uint4*)(g_yh + (size_t)n * 32 + (j0 >> 1)) = *(uint4*)hh;
        } else {
            // z = . + b1 : 8 floats = 2 float4
            float vz[8];
            #pragma unroll
            for (int jp = 0; jp < 4; jp++) {
                float2 f = unpack2(a[jp]);
                vz[2 * jp]     = f.x + sB[j0 - 64 + 2 * jp];
                vz[2 * jp + 1] = f.y + sB[j0 - 64 + 2 * jp + 1];
            }
            float4* dst = (float4*)(g_z + (size_t)n * 64 + (j0 - 64));
            dst[0] = *(float4*)(vz);
            dst[1] = *(float4*)(vz + 4);
        }
    }
}

// ---------------- single-pass scan: decoupled lookback ----------------
__global__ void __launch_bounds__(TB) k_scan() {
    __shared__ int s[2 * TB];
    __shared__ int stile;
    __shared__ int sprefix;
    int t = threadIdx.x;
    if (t == 0) stile = atomicAdd(&g_ticket, 1);
    __syncthreads();
    int tile = stile;
    int base = tile * TILE_ITEMS + t * 8;

    int v[8]; int sum = 0;
    #pragma unroll
    for (int i = 0; i < 8; i++) {
        int idx = base + i;
        v[i] = (idx < N_NODES) ? g_cursor[idx] : 0;
        sum += v[i];
    }
    s[t] = 0;
    int si = TB + t;
    s[si] = sum;
    __syncthreads();
    #pragma unroll
    for (int off = 1; off < TB; off <<= 1) {
        int x = s[si - off];
        __syncthreads();
        s[si] += x;
        __syncthreads();
    }
    int excl_thread = s[si] - sum;
    int block_total = s[2 * TB - 1];

    if (t == 0)
        atomicExch(&g_tstate[tile], (1ull << 32) | (unsigned)block_total);
    if (t < 32) {
        int prefix = 0;
        int b = tile;
        while (b > 0) {
            int look = b - 1 - t;
            unsigned long long st;
            if (look >= 0) {
                do { st = atomicAdd(&g_tstate[look], 0ull); } while ((st >> 32) == 0u);
            } else {
                st = (2ull << 32);
            }
            unsigned status = (unsigned)(st >> 32);
            int val = (int)(st & 0xffffffffu);
            unsigned pmask = __ballot_sync(0xffffffffu, status == 2u);
            int contrib;
            if (pmask) {
                int L = __ffs(pmask) - 1;
                contrib = (t <= L) ? val : 0;
            } else {
                contrib = val;
            }
            #pragma unroll
            for (int o = 16; o > 0; o >>= 1)
                contrib += __shfl_xor_sync(0xffffffffu, contrib, o);
            prefix += contrib;
            if (pmask) break;
            b -= 32;
        }
        if (t == 0) {
            sprefix = prefix;
            atomicExch(&g_tstate[tile],
                       (2ull << 32) | (unsigned)(prefix + block_total));
        }
    }
    __syncthreads();

    int pfx = sprefix + excl_thread;
    #pragma unroll
    for (int i = 0; i < 8; i++) {
        int idx = base + i;
        if (idx < N_NODES) { g_rowptr[idx] = pfx; g_cursor[idx] = pfx; }
        pfx += v[i];
        if (idx == N_NODES - 1) g_rowptr[N_NODES] = pfx;
    }
}

// ---------------- fill: 2 edges/thread ----------------
__global__ void k_fill(const int* __restrict__ ei) {
    int i = blockIdx.x * blockDim.x + threadIdx.x;
    if (i < N_EDGES / 2) {
        int2 s2 = ((const int2*)ei)[i];
        int2 d2 = ((const int2*)(ei + N_EDGES))[i];
        if ((unsigned)s2.x < (unsigned)N_NODES && (unsigned)d2.x < (unsigned)N_NODES) {
            int pos = atomicAdd(&g_cursor[d2.x], 1);
            if ((unsigned)pos < (unsigned)N_EDGES) g_csrc[pos] = s2.x;
        }
        if ((unsigned)s2.y < (unsigned)N_NODES && (unsigned)d2.y < (unsigned)N_NODES) {
            int pos = atomicAdd(&g_cursor[d2.y], 1);
            if ((unsigned)pos < (unsigned)N_EDGES) g_csrc[pos] = s2.y;
        }
    }
}

// ---------------- layer-1 aggregate + relu: warp per node (fp16 gather) -----
__global__ void k_agg1() {
    int n = blockIdx.x * 8 + (threadIdx.x >> 5);
    if (n >= N_NODES) return;
    int lane = threadIdx.x & 31;
    int b = g_rowptr[n], eend = g_rowptr[n + 1];
    int deg = eend - b;
    float ax = 0.f, ay = 0.f;
    int e = b;
    for (; e + 8 <= eend; e += 8) {
        int s0 = g_csrc[e],     s1 = g_csrc[e + 1], s2 = g_csrc[e + 2], s3 = g_csrc[e + 3];
        int s4 = g_csrc[e + 4], s5 = g_csrc[e + 5], s6 = g_csrc[e + 6], s7 = g_csrc[e + 7];
        float2 f0 = __half22float2(g_yh[(size_t)s0 * 32 + lane]);
        float2 f1 = __half22float2(g_yh[(size_t)s1 * 32 + lane]);
        float2 f2 = __half22float2(g_yh[(size_t)s2 * 32 + lane]);
        float2 f3 = __half22float2(g_yh[(size_t)s3 * 32 + lane]);
        float2 f4 = __half22float2(g_yh[(size_t)s4 * 32 + lane]);
        float2 f5 = __half22float2(g_yh[(size_t)s5 * 32 + lane]);
        float2 f6 = __half22float2(g_yh[(size_t)s6 * 32 + lane]);
        float2 f7 = __half22float2(g_yh[(size_t)s7 * 32 + lane]);
        ax += ((f0.x + f1.x) + (f2.x + f3.x)) + ((f4.x + f5.x) + (f6.x + f7.x));
        ay += ((f0.y + f1.y) + (f2.y + f3.y)) + ((f4.y + f5.y) + (f6.y + f7.y));
    }
    for (; e < eend; e++) {
        float2 f = __half22float2(g_yh[(size_t)g_csrc[e] * 32 + lane]);
        ax += f.x; ay += f.y;
    }
    float inv = 1.f / (float)(deg > 0 ? deg : 1);
    size_t o = (size_t)n * 64 + lane * 2;
    g_h[o]     = fmaxf(fmaf(ax, inv, g_z[o]), 0.f);
    g_h[o + 1] = fmaxf(fmaf(ay, inv, g_z[o + 1]), 0.f);
}

// ---------------- layer-2 transform (tiled, pipelined): p(fp16), q ----------
// 64 nodes x 64 outputs; ty=t&15 -> 4 nodes, tx=t>>4 -> 4 outputs (j0=4*tx).
__global__ void __launch_bounds__(TB, 3) k_transform2(const float* __restrict__ Wl,
                                                      const float* __restrict__ Wr,
                                                      const float* __restrict__ b2) {
    __shared__ float sH[64 * 64];    // [k][node]
    __shared__ float sW[64 * 64];    // [k][j]  j<32 -> W2_l, j>=32 -> W2_r
    __shared__ float sB[32];

    int t = threadIdx.x;
    int nbase = blockIdx.x * T_TILE;

    for (int idx = t; idx < 4096; idx += TB) {
        int k = idx >> 6, j = idx & 63;
        sW[idx] = (j < 32) ? Wl[k * 32 + j] : Wr[k * 32 + (j - 32)];
    }
    if (t < 32) sB[t] = b2[t];

    {
        int node = t & 63, kq = t >> 6;
        int ng = nbase + node;
        const float4* hr = (const float4*)(g_h + (size_t)ng * 64 + kq * 16);
        #pragma unroll
        for (int i = 0; i < 4; i++) {
            float4 v = (ng < N_NODES) ? hr[i] : make_float4(0.f, 0.f, 0.f, 0.f);
            int k0 = kq * 16 + i * 4;
            sH[(k0 + 0) * 64 + node] = v.x;
            sH[(k0 + 1) * 64 + node] = v.y;
            sH[(k0 + 2) * 64 + node] = v.z;
            sH[(k0 + 3) * 64 + node] = v.w;
        }
    }
    __syncthreads();

    int ty = t & 15;
    int tx = t >> 4;          // j0 = 4*tx
    const float4*     sH4 = (const float4*)sH;       // row = 16 float4
    const ulonglong2* sWu = (const ulonglong2*)sW;   // row = 16 ulonglong2

    unsigned long long acc[8];   // [node][jpair]: acc[nn*2+jp]
    #pragma unroll
    for (int i = 0; i < 8; i++) acc[i] = 0ull;

    float4     xc = sH4[ty];
    ulonglong2 wa = sWu[tx];
    #pragma unroll 8
    for (int k = 0; k < 64; k++) {
        float4 xn; ulonglong2 wan;
        if (k < 63) {
            xn  = sH4[(k + 1) * 16 + ty];
            wan = sWu[(k + 1) * 16 + tx];
        }
        unsigned long long d0 = packdup(xc.x), d1 = packdup(xc.y);
        unsigned long long d2 = packdup(xc.z), d3 = packdup(xc.w);
        acc[0] = ffma2(wa.x, d0, acc[0]);  acc[1] = ffma2(wa.y, d0, acc[1]);
        acc[2] = ffma2(wa.x, d1, acc[2]);  acc[3] = ffma2(wa.y, d1, acc[3]);
        acc[4] = ffma2(wa.x, d2, acc[4]);  acc[5] = ffma2(wa.y, d2, acc[5]);
        acc[6] = ffma2(wa.x, d3, acc[6]);  acc[7] = ffma2(wa.y, d3, acc[7]);
        xc = xn; wa = wan;
    }

    int j0 = tx * 4;
    #pragma unroll
    for (int nn = 0; nn < 4; nn++) {
        int n = nbase + ty * 4 + nn;
        if (n >= N_NODES) break;
        const unsigned long long* a = acc + nn * 2;
        if (tx < 8) {
            // p -> fp16: 4 outputs = 2 half2 = one 8B store
            float2 f0 = unpack2(a[0]);
            float2 f1 = unpack2(a[1]);
            __half2 hh[2] = { __floats2half2_rn(f0.x, f0.y),
                              __floats2half2_rn(f1.x, f1.y) };
            *(uint2*)(g_ph + (size_t)n * 16 + (j0 >> 1)) = *(uint2*)hh;
        } else {
            // q = . + b2 : 4 floats = 1 float4
            float2 f0 = unpack2(a[0]);
            float2 f1 = unpack2(a[1]);
            float4 vq = make_float4(f0.x + sB[j0 - 32],     f0.y + sB[j0 - 31],
                                    f1.x + sB[j0 - 30],     f1.y + sB[j0 - 29]);
            *(float4*)(g_q + (size_t)n * 32 + (j0 - 32)) = vq;
        }
    }
}

// ---------------- layer-2 aggregate -> output (2 edges per warp) ------------
__global__ void k_agg2(float* __restrict__ out) {
    int n = blockIdx.x * 8 + (threadIdx.x >> 5);
    if (n >= N_NODES) return;
    int lane = threadIdx.x & 31;
    int half = lane >> 4;
    int sub  = lane & 15;
    int b = g_rowptr[n], eend = g_rowptr[n + 1];
    int deg = eend - b;
    float ax = 0.f, ay = 0.f;
    int e = b;
    #pragma unroll 2
    for (; e + 2 <= eend; e += 2) {
        int s = g_csrc[e + half];
        float2 f = __half22float2(g_ph[(size_t)s * 16 + sub]);
        ax += f.x; ay += f.y;
    }
    if (e < eend && half == 0) {
        float2 f = __half22float2(g_ph[(size_t)g_csrc[e] * 16 + sub]);
        ax += f.x; ay += f.y;
    }
    ax += __shfl_xor_sync(0xffffffffu, ax, 16);
    ay += __shfl_xor_sync(0xffffffffu, ay, 16);
    if (half == 0) {
        float inv = 1.f / (float)(deg > 0 ? deg : 1);
        size_t o = (size_t)n * 32 + sub * 2;
        out[o]     = fmaf(ax, inv, g_q[o]);
        out[o + 1] = fmaf(ay, inv, g_q[o + 1]);
    }
}

// ---------------- launch ----------------
extern "C" void kernel_launch(void* const* d_in, const int* in_sizes, int n_in,
                              void* d_out, int out_size) {
    const float* x   = nullptr;
    const int*   ei  = nullptr;
    const float* W1l = nullptr;
    const float* W1r = nullptr;
    const float* b1  = nullptr;
    const float* W2l = nullptr;
    const float* W2r = nullptr;
    const float* b2  = nullptr;
    for (int i = 0; i < n_in; i++) {
        int sz = in_sizes[i];
        const void* p = d_in[i];
        if      (sz == N_NODES * C_IN)   x  = (const float*)p;
        else if (sz == 2 * N_EDGES)      ei = (const int*)p;
        else if (sz == C_IN * C_HID)   { if (!W1l) W1l = (const float*)p; else W1r = (const float*)p; }
        else if (sz == C_HID)            b1 = (const float*)p;
        else if (sz == C_HID * C_OUT)  { if (!W2l) W2l = (const float*)p; else W2r = (const float*)p; }
        else if (sz == C_OUT)            b2 = (const float*)p;
    }
    float* out = (float*)d_out;
    if (!x || !ei || !W1l || !W1r || !b1 || !W2l || !W2r || !b2) return;

    int gridW = (N_NODES + 7) / 8;             // 12500 (warp-per-node, 8 warps/blk)

    k_init<<<GRID_N, TB>>>();
    k_count_t1<<<GRID_T + GRID_E4, TB>>>(ei, x, W1l, W1r, b1);
    k_scan<<<N_TILES, TB>>>();
    k_fill<<<GRID_E2, TB>>>(ei);

    k_agg1<<<gridW, TB>>>();

    k_transform2<<<GRID_T, TB>>>(W2l, W2r, b2);
    k_agg2<<<gridW, TB>>>(out);
}